// round 11
// baseline (speedup 1.0000x reference)
#include <cuda_runtime.h>
#include <cuda_fp16.h>
#include <cstdint>

// TitansMemoryModule — R11: occupancy doubled (1024 thr, <=64 regs/thread).
//   retrieved = k @ W^T ; G1 = k^T k (upper blocks, symmetric) ; G2 = v^T k
// 1024 thr: w0-7 producers (k/v, 2 blocking batches), w8-23 GEMM1 (M=16,N=32),
//           w24-31 reductions (<=4 blocks each, A-frag reuse).

#define D     64
#define TILE  128
#define PH    72
#define DEPTH 4

static constexpr int KBUF  = TILE * PH;
static constexpr int STAGE = 2 * KBUF;
static constexpr int SMEM_HALVES = DEPTH * STAGE + D * PH;
static constexpr int SMEM_BYTES  = SMEM_HALVES * 2;   // 156672 B

__device__ float g_G1[D * D];     // zero-init at load; re-zeroed by final2
__device__ float g_G2[D * D];
__device__ float g_ksum[D];
__device__ float g_sv;
__device__ float g_ss;
__device__ float g_dl;

__device__ __forceinline__ uint32_t sh_u32(const void* p) {
    return (uint32_t)__cvta_generic_to_shared(p);
}
__device__ __forceinline__ void ldsm4(uint32_t& r0, uint32_t& r1, uint32_t& r2, uint32_t& r3, uint32_t a) {
    asm volatile("ldmatrix.sync.aligned.m8n8.x4.shared.b16 {%0,%1,%2,%3},[%4];"
                 : "=r"(r0), "=r"(r1), "=r"(r2), "=r"(r3) : "r"(a));
}
__device__ __forceinline__ void ldsm4t(uint32_t& r0, uint32_t& r1, uint32_t& r2, uint32_t& r3, uint32_t a) {
    asm volatile("ldmatrix.sync.aligned.m8n8.x4.trans.shared.b16 {%0,%1,%2,%3},[%4];"
                 : "=r"(r0), "=r"(r1), "=r"(r2), "=r"(r3) : "r"(a));
}
__device__ __forceinline__ void mma16(float* c,
                                      uint32_t a0, uint32_t a1, uint32_t a2, uint32_t a3,
                                      uint32_t b0, uint32_t b1) {
    asm volatile("mma.sync.aligned.m16n8k16.row.col.f32.f16.f16.f32 "
                 "{%0,%1,%2,%3},{%4,%5,%6,%7},{%8,%9},{%0,%1,%2,%3};"
                 : "+f"(c[0]), "+f"(c[1]), "+f"(c[2]), "+f"(c[3])
                 : "r"(a0), "r"(a1), "r"(a2), "r"(a3), "r"(b0), "r"(b1));
}
__device__ __forceinline__ void mbar_init(uint32_t a, uint32_t cnt) {
    asm volatile("mbarrier.init.shared.b64 [%0], %1;" :: "r"(a), "r"(cnt) : "memory");
}
__device__ __forceinline__ void mbar_arrive(uint32_t a) {
    asm volatile("mbarrier.arrive.shared.b64 _, [%0];" :: "r"(a) : "memory");
}
__device__ __forceinline__ void mbar_wait(uint32_t a, uint32_t parity) {
    asm volatile(
        "{\n\t.reg .pred P;\n"
        "WL_%=:\n\t"
        "mbarrier.try_wait.parity.acquire.cta.shared::cta.b64 P, [%0], %1, 0x989680;\n\t"
        "@P bra WD_%=;\n\t"
        "bra WL_%=;\n"
        "WD_%=:\n\t}"
        :: "r"(a), "r"(parity) : "memory");
}

// ---- reduction fragment helpers ----
__device__ __forceinline__ void ldAfrag(uint32_t* f, const __half* mb, int sb, int ar, int lane) {
    const int asel = ((lane >> 4) << 3) + (lane & 7);
    const int aoff = ((lane >> 3) & 1) * 8;
    ldsm4t(f[0], f[1], f[2], f[3], sh_u32(&mb[(sb + asel) * PH + ar * 16 + aoff]));
}
__device__ __forceinline__ void ldBfrag(uint32_t* f, const __half* kb, int sb, int ac, int lane) {
    const int bsel = ((lane >> 3) & 1) * 8 + (lane & 7);
    const int boff = (lane >> 4) * 8;
    ldsm4t(f[0], f[1], f[2], f[3], sh_u32(&kb[(sb + bsel) * PH + ac * 16 + boff]));
}
__device__ __forceinline__ void bmma(float* acc, const uint32_t* A, const uint32_t* B) {
    mma16(acc,     A[0], A[1], A[2], A[3], B[0], B[1]);
    mma16(acc + 4, A[0], A[1], A[2], A[3], B[2], B[3]);
}

// reduction per-warp tile routines (kk-outer, A reuse, B per block)
__device__ __forceinline__ void rw0(float (&acc)[4][8], const __half* kb, const __half*, int lane) {
#pragma unroll
    for (int kk = 0; kk < 8; kk++) {
        const int sb = kk * 16;
        uint32_t A[4], B[4];
        ldAfrag(A, kb, sb, 0, lane);
        ldBfrag(B, kb, sb, 0, lane); bmma(acc[0], A, B);
        ldBfrag(B, kb, sb, 1, lane); bmma(acc[1], A, B);
        ldBfrag(B, kb, sb, 2, lane); bmma(acc[2], A, B);
    }
}
__device__ __forceinline__ void rw1(float (&acc)[4][8], const __half* kb, const __half*, int lane) {
#pragma unroll
    for (int kk = 0; kk < 8; kk++) {
        const int sb = kk * 16;
        uint32_t A0[4], A1[4], B3[4], B[4];
        ldAfrag(A0, kb, sb, 0, lane); ldAfrag(A1, kb, sb, 1, lane);
        ldBfrag(B3, kb, sb, 3, lane);
        bmma(acc[0], A0, B3);
        ldBfrag(B, kb, sb, 1, lane); bmma(acc[1], A1, B);
        ldBfrag(B, kb, sb, 2, lane); bmma(acc[2], A1, B);
        bmma(acc[3], A1, B3);
    }
}
__device__ __forceinline__ void rw2(float (&acc)[4][8], const __half* kb, const __half*, int lane) {
#pragma unroll
    for (int kk = 0; kk < 8; kk++) {
        const int sb = kk * 16;
        uint32_t A2[4], A3[4], B[4];
        ldAfrag(A2, kb, sb, 2, lane); ldAfrag(A3, kb, sb, 3, lane);
        ldBfrag(B, kb, sb, 2, lane); bmma(acc[0], A2, B);
        ldBfrag(B, kb, sb, 3, lane); bmma(acc[1], A2, B); bmma(acc[2], A3, B);
    }
}
__device__ __forceinline__ void rwV4(float (&acc)[4][8], const __half* kb, const __half* vb,
                                     int ar, int lane) {
#pragma unroll
    for (int kk = 0; kk < 8; kk++) {
        const int sb = kk * 16;
        uint32_t A[4], B[4];
        ldAfrag(A, vb, sb, ar, lane);
        ldBfrag(B, kb, sb, 0, lane); bmma(acc[0], A, B);
        ldBfrag(B, kb, sb, 1, lane); bmma(acc[1], A, B);
        ldBfrag(B, kb, sb, 2, lane); bmma(acc[2], A, B);
        ldBfrag(B, kb, sb, 3, lane); bmma(acc[3], A, B);
    }
}
__device__ __forceinline__ void rwV2(float (&acc)[4][8], const __half* kb, const __half* vb,
                                     int ac0, int lane) {
#pragma unroll
    for (int kk = 0; kk < 8; kk++) {
        const int sb = kk * 16;
        uint32_t A[4], B[4];
        ldAfrag(A, vb, sb, 3, lane);
        ldBfrag(B, kb, sb, ac0, lane);     bmma(acc[0], A, B);
        ldBfrag(B, kb, sb, ac0 + 1, lane); bmma(acc[1], A, B);
    }
}

// writeout tables: enc = src<<4 | ar<<2 | ac
static __device__ const int RW_TBL[8][4] = {
    { 0,  1,  2,  0},
    { 3,  5,  6,  7},
    {10, 11, 15,  0},
    {16, 17, 18, 19},
    {20, 21, 22, 23},
    {24, 25, 26, 27},
    {28, 29,  0,  0},
    {30, 31,  0,  0},
};
static __device__ const int RW_CNT[8] = {3, 4, 3, 4, 4, 4, 2, 2};

__global__ __launch_bounds__(1024, 1)
void titans_main_kernel(const float* __restrict__ kmat,
                        const float* __restrict__ vmat,
                        const float* __restrict__ W,
                        float* __restrict__ ret,
                        int N) {
    extern __shared__ __half sh[];
    __shared__ uint64_t mbar[2 * DEPTH];   // [0..3] full, [4..7] empty
    __half* wsh = sh + DEPTH * STAGE;

    const int tid  = threadIdx.x;
    const int lane = tid & 31;
    const int warp = tid >> 5;

    if (tid == 0) {
#pragma unroll
        for (int s = 0; s < DEPTH; s++) {
            mbar_init(sh_u32(&mbar[s]), 256);          // full: 256 producer threads
            mbar_init(sh_u32(&mbar[DEPTH + s]), 24);   // empty: 16 gemm1 + 8 red warps
        }
    }
    for (int i = tid; i < D * D; i += 1024)
        wsh[(i >> 6) * PH + (i & 63)] = __float2half(W[i]);
    __syncthreads();

    const int grid   = gridDim.x;
    const int ntiles = N / TILE;

    if (warp < 8) {
        // ======== PRODUCERS (256 thr): tid<128 -> k, else v; 16 f4/thread in 2 batches ========
        const bool isK  = tid < 128;
        const int  pt   = tid & 127;
        const int  qcol = (pt & 15) * 4;
        const int  rb   = pt >> 4;                   // row base
        const float4* src = reinterpret_cast<const float4*>(isK ? kmat : vmat);
        const int  boff = isK ? 0 : KBUF;

        float acc4[4] = {0.f, 0.f, 0.f, 0.f};

        int stage = 0, phase = 1;
        for (int tile = blockIdx.x; tile < ntiles; tile += grid) {
            mbar_wait(sh_u32(&mbar[DEPTH + stage]), phase);
            __half* dst = sh + stage * STAGE + boff;
            const float4* t = src + (size_t)tile * 2048;

            float4 c[8];
#pragma unroll
            for (int j = 0; j < 8; j++) c[j] = __ldcs(&t[pt + j * 128]);
#pragma unroll
            for (int j = 0; j < 8; j++) {
                float4 x = c[j];
                int r = rb + j * 8;
                if (isK) { acc4[0] += x.x; acc4[1] += x.y; acc4[2] += x.z; acc4[3] += x.w; }
                else     { acc4[0] += x.x * x.x + x.y * x.y + x.z * x.z + x.w * x.w; }
                __half2 h01 = __floats2half2_rn(x.x, x.y);
                __half2 h23 = __floats2half2_rn(x.z, x.w);
                *reinterpret_cast<uint2*>(&dst[r * PH + qcol]) =
                    make_uint2(*reinterpret_cast<uint32_t*>(&h01), *reinterpret_cast<uint32_t*>(&h23));
            }
#pragma unroll
            for (int j = 0; j < 8; j++) c[j] = __ldcs(&t[pt + (j + 8) * 128]);
#pragma unroll
            for (int j = 0; j < 8; j++) {
                float4 x = c[j];
                int r = rb + (j + 8) * 8;
                if (isK) { acc4[0] += x.x; acc4[1] += x.y; acc4[2] += x.z; acc4[3] += x.w; }
                else     { acc4[0] += x.x * x.x + x.y * x.y + x.z * x.z + x.w * x.w; }
                __half2 h01 = __floats2half2_rn(x.x, x.y);
                __half2 h23 = __floats2half2_rn(x.z, x.w);
                *reinterpret_cast<uint2*>(&dst[r * PH + qcol]) =
                    make_uint2(*reinterpret_cast<uint32_t*>(&h01), *reinterpret_cast<uint32_t*>(&h23));
            }
            mbar_arrive(sh_u32(&mbar[stage]));
            stage++; if (stage == DEPTH) { stage = 0; phase ^= 1; }
        }

        if (isK) {
#pragma unroll
            for (int c = 0; c < 4; c++) atomicAdd(&g_ksum[qcol + c], acc4[c]);
        } else {
            float sv = acc4[0];
#pragma unroll
            for (int off = 16; off > 0; off >>= 1) sv += __shfl_xor_sync(0xFFFFFFFF, sv, off);
            if (lane == 0) atomicAdd(&g_sv, sv);
        }

    } else if (warp < 24) {
        // ======== GEMM1 (16 warps): each M=16, N=32 ========
        const int g    = warp - 8;
        const int row0 = (g >> 1) * 16;
        const int ch   = (g & 1) * 32;
        const int lp = lane >> 2, lq = lane & 3;

        uint32_t wr[4][2][4];   // W fragments for this warp's 32 columns
#pragma unroll
        for (int kk = 0; kk < 4; kk++)
#pragma unroll
            for (int j = 0; j < 2; j++) {
                const int bt = ((g & 1) * 4 + 2 * j + (lane >> 4)) * 8 + (lane & 7);
                const int bc = kk * 16 + ((lane >> 3) & 1) * 8;
                ldsm4(wr[kk][j][0], wr[kk][j][1], wr[kk][j][2], wr[kk][j][3],
                      sh_u32(&wsh[bt * PH + bc]));
            }

        int stage = 0, phase = 0;
        for (int tile = blockIdx.x; tile < ntiles; tile += grid) {
            mbar_wait(sh_u32(&mbar[stage]), phase);
            const __half* kb = sh + stage * STAGE;

            float c1[4][4];
#pragma unroll
            for (int n = 0; n < 4; n++)
#pragma unroll
                for (int i = 0; i < 4; i++) c1[n][i] = 0.0f;

#pragma unroll
            for (int kk = 0; kk < 4; kk++) {
                uint32_t a0, a1, a2, a3;
                ldsm4(a0, a1, a2, a3,
                      sh_u32(&kb[(row0 + (lane & 15)) * PH + kk * 16 + ((lane >> 4) << 3)]));
#pragma unroll
                for (int j = 0; j < 2; j++) {
                    mma16(c1[2 * j],     a0, a1, a2, a3, wr[kk][j][0], wr[kk][j][1]);
                    mma16(c1[2 * j + 1], a0, a1, a2, a3, wr[kk][j][2], wr[kk][j][3]);
                }
            }
            if (lane == 0) mbar_arrive(sh_u32(&mbar[DEPTH + stage]));

            const size_t gr0 = (size_t)(tile * TILE + row0 + lp) * D;
#pragma unroll
            for (int n = 0; n < 4; n++) {
                const int col = ch + n * 8 + 2 * lq;
                *reinterpret_cast<float2*>(&ret[gr0 + col])         = make_float2(c1[n][0], c1[n][1]);
                *reinterpret_cast<float2*>(&ret[gr0 + 8 * D + col]) = make_float2(c1[n][2], c1[n][3]);
            }
            stage++; if (stage == DEPTH) { stage = 0; phase ^= 1; }
        }

    } else {
        // ======== Reductions (8 warps): symmetric G1 + G2 ========
        const int r  = warp - 24;
        const int lp = lane >> 2, lq = lane & 3;

        float acc[4][8];
#pragma unroll
        for (int b = 0; b < 4; b++)
#pragma unroll
            for (int i = 0; i < 8; i++) acc[b][i] = 0.0f;

        int stage = 0, phase = 0;
        for (int tile = blockIdx.x; tile < ntiles; tile += grid) {
            mbar_wait(sh_u32(&mbar[stage]), phase);
            const __half* kb = sh + stage * STAGE;
            const __half* vb = kb + KBUF;

            switch (r) {
                case 0: rw0(acc, kb, vb, lane); break;
                case 1: rw1(acc, kb, vb, lane); break;
                case 2: rw2(acc, kb, vb, lane); break;
                case 3: rwV4(acc, kb, vb, 0, lane); break;
                case 4: rwV4(acc, kb, vb, 1, lane); break;
                case 5: rwV4(acc, kb, vb, 2, lane); break;
                case 6: rwV2(acc, kb, vb, 0, lane); break;
                default: rwV2(acc, kb, vb, 2, lane); break;
            }
            if (lane == 0) mbar_arrive(sh_u32(&mbar[DEPTH + stage]));
            stage++; if (stage == DEPTH) { stage = 0; phase ^= 1; }
        }

        const int cnt = RW_CNT[r];
        for (int b = 0; b < cnt; b++) {
            const int enc = RW_TBL[r][b];
            const int src = (enc >> 4) & 1, ar = (enc >> 2) & 3, ac = enc & 3;
            float* gd = src ? g_G2 : g_G1;
            const int r0 = (ar * 16 + lp) * D + ac * 16;
            const int r1 = (ar * 16 + 8 + lp) * D + ac * 16;
            atomicAdd(&gd[r0 + 2 * lq],         acc[b][0]);
            atomicAdd(&gd[r0 + 2 * lq + 1],     acc[b][1]);
            atomicAdd(&gd[r1 + 2 * lq],         acc[b][2]);
            atomicAdd(&gd[r1 + 2 * lq + 1],     acc[b][3]);
            atomicAdd(&gd[r0 + 8 + 2 * lq],     acc[b][4]);
            atomicAdd(&gd[r0 + 8 + 2 * lq + 1], acc[b][5]);
            atomicAdd(&gd[r1 + 8 + 2 * lq],     acc[b][6]);
            atomicAdd(&gd[r1 + 8 + 2 * lq + 1], acc[b][7]);
        }
    }
}

// gates helper: warps 0-2 each compute one gate (identical across blocks)
__device__ __forceinline__ void compute_gates(float* gates_sh, const float* gate_w,
                                              const float* gate_b, int warp, int lane, int N) {
    if (warp < 3) {
        const float invN = 1.0f / (float)N;
        float s = gate_w[warp * D + lane]      * (g_ksum[lane]      * invN)
                + gate_w[warp * D + 32 + lane] * (g_ksum[32 + lane] * invN);
#pragma unroll
        for (int off = 16; off > 0; off >>= 1)
            s += __shfl_xor_sync(0xFFFFFFFF, s, off);
        if (lane == 0)
            gates_sh[warp] = 1.0f / (1.0f + __expf(-(s + gate_b[warp])));
    }
}

// final1: 32 blocks x 128 threads
__global__ void titans_final1(const float* __restrict__ W,
                              const float* __restrict__ gate_w,
                              const float* __restrict__ gate_b,
                              const float* __restrict__ S,
                              float* __restrict__ out,
                              int N) {
    __shared__ float G1m[D * D];
    __shared__ float W2[2 * D];
    __shared__ float gates_sh[3];
    __shared__ float red[128], red2[128];
    const int tid  = threadIdx.x;
    const int bid  = blockIdx.x;
    const int lane = tid & 31;
    const int warp = tid >> 5;
    const float numel = (float)N * (float)D;

    const size_t loss_off = (size_t)N * D;
    const size_t nw_off   = loss_off + 1;
    const size_t ns_off   = nw_off + D * D;

    compute_gates(gates_sh, gate_w, gate_b, warp, lane, N);

    for (int i = tid; i < D * D; i += 128) {
        const int j = i >> 6, d = i & 63;
        G1m[i] = ((j >> 4) <= (d >> 4)) ? g_G1[i] : g_G1[(d << 6) | j];
    }
    W2[tid] = W[bid * 128 + tid];
    __syncthreads();

    const float alpha = gates_sh[0];
    const float eta   = gates_sh[1];
    const float theta = gates_sh[2];

    const int idx = bid * 128 + tid;
    const int jr  = tid >> 6;
    const int dp  = idx & 63;

    float a = 0.0f;
#pragma unroll 8
    for (int d = 0; d < D; d++)
        a += W2[jr * D + d] * G1m[d * D + dp];

    const float w  = W2[jr * D + dp];
    const float g2 = g_G2[idx];
    float g = (a - g2) * (2.0f / numel);
    g = fminf(1.0f, fmaxf(-1.0f, g));
    const float ns = eta * S[idx] - 0.01f * theta * g;
    const float nw = (1.0f - alpha) * w + ns;
    out[ns_off + idx] = ns;
    out[nw_off + idx] = nw;

    red[tid]  = nw * nw;
    red2[tid] = (a - 2.0f * g2) * w;
    __syncthreads();
#pragma unroll
    for (int s = 64; s > 0; s >>= 1) {
        if (tid < s) { red[tid] += red[tid + s]; red2[tid] += red2[tid + s]; }
        __syncthreads();
    }
    if (tid == 0) {
        atomicAdd(&g_ss, red[0]);
        atomicAdd(&g_dl, red2[0]);
    }
}

// final2: 1 block — scale new_W, loss, gates, re-zero scratch
__global__ void titans_final2(const float* __restrict__ gate_w,
                              const float* __restrict__ gate_b,
                              float* __restrict__ out,
                              int N) {
    __shared__ float gates_sh[3];
    __shared__ float sc_sh;
    const int tid  = threadIdx.x;
    const int lane = tid & 31;
    const int warp = tid >> 5;
    const float numel = (float)N * (float)D;

    const size_t loss_off = (size_t)N * D;
    const size_t nw_off   = loss_off + 1;
    const size_t g_off    = nw_off + 2 * D * D;

    compute_gates(gates_sh, gate_w, gate_b, warp, lane, N);
    if (tid == 0) {
        float wnorm = sqrtf(g_ss);
        sc_sh = (wnorm > 10.0f) ? (10.0f / (wnorm + 1e-8f)) : 1.0f;
        out[loss_off] = (g_sv + g_dl) / numel;
    }
    __syncthreads();
    const float sc = sc_sh;
    for (int i = tid; i < D * D; i += 256)
        out[nw_off + i] *= sc;
    if (tid < 3) out[g_off + tid] = gates_sh[tid];

    __syncthreads();
    for (int i = tid; i < D * D; i += 256) { g_G1[i] = 0.0f; g_G2[i] = 0.0f; }
    if (tid < D) g_ksum[tid] = 0.0f;
    if (tid == 0) { g_sv = 0.0f; g_ss = 0.0f; g_dl = 0.0f; }
}

extern "C" void kernel_launch(void* const* d_in, const int* in_sizes, int n_in,
                              void* d_out, int out_size) {
    const float* k  = (const float*)d_in[0];
    const float* v  = (const float*)d_in[1];
    const float* W  = (const float*)d_in[2];
    const float* gw = (const float*)d_in[3];
    const float* gb = (const float*)d_in[4];
    const float* S  = (const float*)d_in[5];
    float* out = (float*)d_out;

    const int N = in_sizes[0] / D;

    cudaFuncSetAttribute(titans_main_kernel,
                         cudaFuncAttributeMaxDynamicSharedMemorySize, SMEM_BYTES);

    titans_main_kernel<<<148, 1024, SMEM_BYTES>>>(k, v, W, out, N);
    titans_final1<<<32, 128>>>(W, gw, gb, S, out, N);
    titans_final2<<<1, 256>>>(gw, gb, out, N);
}

// round 12
// speedup vs baseline: 1.1638x; 1.1638x over previous
#include <cuda_runtime.h>
#include <cuda_fp16.h>
#include <cstdint>

// TitansMemoryModule — R12: R10 structure + cheap barriers, early empty-arrive, DEPTH=5, stcs.
//   retrieved = k @ W^T ; G1 = k^T k (upper blocks, symmetric) ; G2 = v^T k
// 512 thr: w0-7 producers (k/v, cross-tile prefetch), w8-11 GEMM1 (M=32), w12-15 reductions.

#define D     64
#define TILE  128
#define PH    72
#define DEPTH 5

static constexpr int KBUF  = TILE * PH;
static constexpr int STAGE = 2 * KBUF;
static constexpr int SMEM_HALVES = DEPTH * STAGE + D * PH;
static constexpr int SMEM_BYTES  = SMEM_HALVES * 2;   // 193536 B

__device__ float g_G1[D * D];     // zero-init at load; re-zeroed by final2
__device__ float g_G2[D * D];
__device__ float g_ksum[D];
__device__ float g_sv;
__device__ float g_ss;
__device__ float g_dl;

__device__ __forceinline__ uint32_t sh_u32(const void* p) {
    return (uint32_t)__cvta_generic_to_shared(p);
}
__device__ __forceinline__ void ldsm4(uint32_t& r0, uint32_t& r1, uint32_t& r2, uint32_t& r3, uint32_t a) {
    asm volatile("ldmatrix.sync.aligned.m8n8.x4.shared.b16 {%0,%1,%2,%3},[%4];"
                 : "=r"(r0), "=r"(r1), "=r"(r2), "=r"(r3) : "r"(a));
}
__device__ __forceinline__ void ldsm4t(uint32_t& r0, uint32_t& r1, uint32_t& r2, uint32_t& r3, uint32_t a) {
    asm volatile("ldmatrix.sync.aligned.m8n8.x4.trans.shared.b16 {%0,%1,%2,%3},[%4];"
                 : "=r"(r0), "=r"(r1), "=r"(r2), "=r"(r3) : "r"(a));
}
__device__ __forceinline__ void mma16(float* c,
                                      uint32_t a0, uint32_t a1, uint32_t a2, uint32_t a3,
                                      uint32_t b0, uint32_t b1) {
    asm volatile("mma.sync.aligned.m16n8k16.row.col.f32.f16.f16.f32 "
                 "{%0,%1,%2,%3},{%4,%5,%6,%7},{%8,%9},{%0,%1,%2,%3};"
                 : "+f"(c[0]), "+f"(c[1]), "+f"(c[2]), "+f"(c[3])
                 : "r"(a0), "r"(a1), "r"(a2), "r"(a3), "r"(b0), "r"(b1));
}
__device__ __forceinline__ void mbar_init(uint32_t a, uint32_t cnt) {
    asm volatile("mbarrier.init.shared.b64 [%0], %1;" :: "r"(a), "r"(cnt) : "memory");
}
__device__ __forceinline__ void mbar_arrive(uint32_t a) {
    asm volatile("mbarrier.arrive.shared.b64 _, [%0];" :: "r"(a) : "memory");
}
__device__ __forceinline__ void mbar_wait(uint32_t a, uint32_t parity) {
    asm volatile(
        "{\n\t.reg .pred P;\n"
        "WL_%=:\n\t"
        "mbarrier.try_wait.parity.acquire.cta.shared::cta.b64 P, [%0], %1, 0x989680;\n\t"
        "@P bra WD_%=;\n\t"
        "bra WL_%=;\n"
        "WD_%=:\n\t}"
        :: "r"(a), "r"(parity) : "memory");
}

// ---- reduction fragment helpers ----
__device__ __forceinline__ void ldAfrag(uint32_t* f, const __half* mb, int sb, int ar, int lane) {
    const int asel = ((lane >> 4) << 3) + (lane & 7);
    const int aoff = ((lane >> 3) & 1) * 8;
    ldsm4t(f[0], f[1], f[2], f[3], sh_u32(&mb[(sb + asel) * PH + ar * 16 + aoff]));
}
__device__ __forceinline__ void ldBfrag(uint32_t* f, const __half* kb, int sb, int ac, int lane) {
    const int bsel = ((lane >> 3) & 1) * 8 + (lane & 7);
    const int boff = (lane >> 4) * 8;
    ldsm4t(f[0], f[1], f[2], f[3], sh_u32(&kb[(sb + bsel) * PH + ac * 16 + boff]));
}
__device__ __forceinline__ void bmma(float* acc, const uint32_t* A, const uint32_t* B) {
    mma16(acc,     A[0], A[1], A[2], A[3], B[0], B[1]);
    mma16(acc + 4, A[0], A[1], A[2], A[3], B[2], B[3]);
}

// writeout tables: enc = src<<4 | ar<<2 | ac
static __device__ const int RW_TBL[4][7] = {
    { 0,  1,  2,  3,  5,  6,  7},
    {10, 11, 15, 16, 17, 18, 19},
    {20, 21, 22, 23, 24, 25, 25},
    {26, 27, 28, 29, 30, 31, 31},
};
static __device__ const int RW_CNT[4] = {7, 7, 6, 6};

// Per-tile reduction routines. Arrive-empty is issued INSIDE the last kk
// iteration, after its ldsm loads and before its mma chain (frees the stage
// ~200-300cyc earlier; producer wait+wakeup latency >> LDSM in-flight window).
__device__ __forceinline__ void red_tile_w0(float (&acc)[7][8], const __half* kb, const __half*,
                                            int lane, uint32_t ebar) {
#pragma unroll
    for (int kk = 0; kk < 8; kk++) {
        const int sb = kk * 16;
        uint32_t A0[4], A1[4], B[4][4];
        ldAfrag(A0, kb, sb, 0, lane); ldAfrag(A1, kb, sb, 1, lane);
#pragma unroll
        for (int ac = 0; ac < 4; ac++) ldBfrag(B[ac], kb, sb, ac, lane);
        if (kk == 7 && lane == 0) mbar_arrive(ebar);
        bmma(acc[0], A0, B[0]); bmma(acc[1], A0, B[1]);
        bmma(acc[2], A0, B[2]); bmma(acc[3], A0, B[3]);
        bmma(acc[4], A1, B[1]); bmma(acc[5], A1, B[2]); bmma(acc[6], A1, B[3]);
    }
}
__device__ __forceinline__ void red_tile_w1(float (&acc)[7][8], const __half* kb, const __half* vb,
                                            int lane, uint32_t ebar) {
#pragma unroll
    for (int kk = 0; kk < 8; kk++) {
        const int sb = kk * 16;
        uint32_t A2[4], A3[4], AV[4], B[4][4];
        ldAfrag(A2, kb, sb, 2, lane); ldAfrag(A3, kb, sb, 3, lane); ldAfrag(AV, vb, sb, 0, lane);
#pragma unroll
        for (int ac = 0; ac < 4; ac++) ldBfrag(B[ac], kb, sb, ac, lane);
        if (kk == 7 && lane == 0) mbar_arrive(ebar);
        bmma(acc[0], A2, B[2]); bmma(acc[1], A2, B[3]); bmma(acc[2], A3, B[3]);
        bmma(acc[3], AV, B[0]); bmma(acc[4], AV, B[1]);
        bmma(acc[5], AV, B[2]); bmma(acc[6], AV, B[3]);
    }
}
__device__ __forceinline__ void red_tile_w2(float (&acc)[7][8], const __half* kb, const __half* vb,
                                            int lane, uint32_t ebar) {
#pragma unroll
    for (int kk = 0; kk < 8; kk++) {
        const int sb = kk * 16;
        uint32_t A1[4], A2[4], B[4][4];
        ldAfrag(A1, vb, sb, 1, lane); ldAfrag(A2, vb, sb, 2, lane);
#pragma unroll
        for (int ac = 0; ac < 4; ac++) ldBfrag(B[ac], kb, sb, ac, lane);
        if (kk == 7 && lane == 0) mbar_arrive(ebar);
        bmma(acc[0], A1, B[0]); bmma(acc[1], A1, B[1]);
        bmma(acc[2], A1, B[2]); bmma(acc[3], A1, B[3]);
        bmma(acc[4], A2, B[0]); bmma(acc[5], A2, B[1]);
    }
}
__device__ __forceinline__ void red_tile_w3(float (&acc)[7][8], const __half* kb, const __half* vb,
                                            int lane, uint32_t ebar) {
#pragma unroll
    for (int kk = 0; kk < 8; kk++) {
        const int sb = kk * 16;
        uint32_t A2[4], A3[4], B[4][4];
        ldAfrag(A2, vb, sb, 2, lane); ldAfrag(A3, vb, sb, 3, lane);
#pragma unroll
        for (int ac = 0; ac < 4; ac++) ldBfrag(B[ac], kb, sb, ac, lane);
        if (kk == 7 && lane == 0) mbar_arrive(ebar);
        bmma(acc[0], A2, B[2]); bmma(acc[1], A2, B[3]);
        bmma(acc[2], A3, B[0]); bmma(acc[3], A3, B[1]);
        bmma(acc[4], A3, B[2]); bmma(acc[5], A3, B[3]);
    }
}

__global__ __launch_bounds__(512, 1)
void titans_main_kernel(const float* __restrict__ kmat,
                        const float* __restrict__ vmat,
                        const float* __restrict__ W,
                        float* __restrict__ ret,
                        int N) {
    extern __shared__ __half sh[];
    __shared__ uint64_t mbar[2 * DEPTH];   // [0..DEPTH) full, [DEPTH..2*DEPTH) empty
    __half* wsh = sh + DEPTH * STAGE;

    const int tid  = threadIdx.x;
    const int lane = tid & 31;
    const int warp = tid >> 5;

    if (tid == 0) {
#pragma unroll
        for (int s = 0; s < DEPTH; s++) {
            mbar_init(sh_u32(&mbar[s]), 8);            // full: 8 producer WARPS
            mbar_init(sh_u32(&mbar[DEPTH + s]), 8);    // empty: 8 consumer warps
        }
    }
    for (int i = tid; i < D * D; i += 512)
        wsh[(i >> 6) * PH + (i & 63)] = __float2half(W[i]);
    __syncthreads();

    const int grid   = gridDim.x;
    const int ntiles = N / TILE;

    if (warp < 8) {
        // ======== PRODUCERS: w0-3 k, w4-7 v (cross-tile register prefetch) ========
        const bool isK  = warp < 4;
        const int  pt   = isK ? tid : (tid - 128);
        const int  qcol = (pt & 15) * 4;
        const float4* src = reinterpret_cast<const float4*>(isK ? kmat : vmat);
        const int  boff = isK ? 0 : KBUF;

        float acc4[4] = {0.f, 0.f, 0.f, 0.f};

        float4 c0[8], c1r[8];
        {
            const float4* t0 = src + (size_t)blockIdx.x * 2048;
#pragma unroll
            for (int j = 0; j < 8; j++) c0[j]  = __ldcs(&t0[pt + j * 128]);
#pragma unroll
            for (int j = 0; j < 8; j++) c1r[j] = __ldcs(&t0[pt + (j + 8) * 128]);
        }

        int stage = 0, phase = 1;
        for (int tile = blockIdx.x; tile < ntiles; tile += grid) {
            int nt = tile + grid; if (nt >= ntiles) nt = tile;
            const float4* tn = src + (size_t)nt * 2048;

            mbar_wait(sh_u32(&mbar[DEPTH + stage]), phase);
            __half* dst = sh + stage * STAGE + boff;

#pragma unroll
            for (int j = 0; j < 8; j++) {
                float4 x = c0[j];
                int r = (pt + j * 128) >> 4;
                if (isK) { acc4[0] += x.x; acc4[1] += x.y; acc4[2] += x.z; acc4[3] += x.w; }
                else     { acc4[0] += x.x * x.x + x.y * x.y + x.z * x.z + x.w * x.w; }
                __half2 h01 = __floats2half2_rn(x.x, x.y);
                __half2 h23 = __floats2half2_rn(x.z, x.w);
                *reinterpret_cast<uint2*>(&dst[r * PH + qcol]) =
                    make_uint2(*reinterpret_cast<uint32_t*>(&h01), *reinterpret_cast<uint32_t*>(&h23));
            }
#pragma unroll
            for (int j = 0; j < 8; j++) c0[j] = __ldcs(&tn[pt + j * 128]);

#pragma unroll
            for (int j = 0; j < 8; j++) {
                float4 x = c1r[j];
                int r = (pt + (j + 8) * 128) >> 4;
                if (isK) { acc4[0] += x.x; acc4[1] += x.y; acc4[2] += x.z; acc4[3] += x.w; }
                else     { acc4[0] += x.x * x.x + x.y * x.y + x.z * x.z + x.w * x.w; }
                __half2 h01 = __floats2half2_rn(x.x, x.y);
                __half2 h23 = __floats2half2_rn(x.z, x.w);
                *reinterpret_cast<uint2*>(&dst[r * PH + qcol]) =
                    make_uint2(*reinterpret_cast<uint32_t*>(&h01), *reinterpret_cast<uint32_t*>(&h23));
            }
#pragma unroll
            for (int j = 0; j < 8; j++) c1r[j] = __ldcs(&tn[pt + (j + 8) * 128]);

            __syncwarp();
            if (lane == 0) mbar_arrive(sh_u32(&mbar[stage]));   // per-WARP full arrive
            stage++; if (stage == DEPTH) { stage = 0; phase ^= 1; }
        }

        if (isK) {
#pragma unroll
            for (int c = 0; c < 4; c++) atomicAdd(&g_ksum[qcol + c], acc4[c]);
        } else {
            float sv = acc4[0];
#pragma unroll
            for (int off = 16; off > 0; off >>= 1) sv += __shfl_xor_sync(0xFFFFFFFF, sv, off);
            if (lane == 0) atomicAdd(&g_sv, sv);
        }

    } else if (warp < 12) {
        // ======== GEMM1 warps (4): each M=32 (two 16-row stripes), N=64 ========
        const int widx = warp - 8;
        const int lp = lane >> 2, lq = lane & 3;

        uint32_t wr[4][4][4];
#pragma unroll
        for (int kk = 0; kk < 4; kk++)
#pragma unroll
            for (int j = 0; j < 4; j++) {
                const int bt = (2 * j + (lane >> 4)) * 8 + (lane & 7);
                const int bc = kk * 16 + ((lane >> 3) & 1) * 8;
                ldsm4(wr[kk][j][0], wr[kk][j][1], wr[kk][j][2], wr[kk][j][3],
                      sh_u32(&wsh[bt * PH + bc]));
            }

        int stage = 0, phase = 0;
        for (int tile = blockIdx.x; tile < ntiles; tile += grid) {
            mbar_wait(sh_u32(&mbar[stage]), phase);
            const __half* kb = sh + stage * STAGE;

#pragma unroll
            for (int s2 = 0; s2 < 2; s2++) {
                const int rbase = widx * 32 + s2 * 16;
                uint32_t af[4][4];
#pragma unroll
                for (int kk = 0; kk < 4; kk++)
                    ldsm4(af[kk][0], af[kk][1], af[kk][2], af[kk][3],
                          sh_u32(&kb[(rbase + (lane & 15)) * PH + kk * 16 + ((lane >> 4) << 3)]));
                if (s2 == 1 && lane == 0) mbar_arrive(sh_u32(&mbar[DEPTH + stage]));

                float c1[8][4];
#pragma unroll
                for (int n = 0; n < 8; n++)
#pragma unroll
                    for (int i = 0; i < 4; i++) c1[n][i] = 0.0f;
#pragma unroll
                for (int kk = 0; kk < 4; kk++)
#pragma unroll
                    for (int j = 0; j < 4; j++) {
                        mma16(c1[2 * j],     af[kk][0], af[kk][1], af[kk][2], af[kk][3],
                              wr[kk][j][0], wr[kk][j][1]);
                        mma16(c1[2 * j + 1], af[kk][0], af[kk][1], af[kk][2], af[kk][3],
                              wr[kk][j][2], wr[kk][j][3]);
                    }

                const size_t gr0 = (size_t)(tile * TILE + rbase + lp) * D;
#pragma unroll
                for (int n = 0; n < 8; n++) {
                    const int col = n * 8 + 2 * lq;
                    __stcs(reinterpret_cast<float2*>(&ret[gr0 + col]),
                           make_float2(c1[n][0], c1[n][1]));
                    __stcs(reinterpret_cast<float2*>(&ret[gr0 + 8 * D + col]),
                           make_float2(c1[n][2], c1[n][3]));
                }
            }
            stage++; if (stage == DEPTH) { stage = 0; phase ^= 1; }
        }

    } else {
        // ======== Reduction warps (4): symmetric G1 + G2, early empty-arrive ========
        const int ridx = warp - 12;
        const int lp = lane >> 2, lq = lane & 3;

        float acc[7][8];
#pragma unroll
        for (int b = 0; b < 7; b++)
#pragma unroll
            for (int i = 0; i < 8; i++) acc[b][i] = 0.0f;

        int stage = 0, phase = 0;
        for (int tile = blockIdx.x; tile < ntiles; tile += grid) {
            mbar_wait(sh_u32(&mbar[stage]), phase);
            const __half* kb = sh + stage * STAGE;
            const __half* vb = kb + KBUF;
            const uint32_t ebar = sh_u32(&mbar[DEPTH + stage]);

            if      (ridx == 0) red_tile_w0(acc, kb, vb, lane, ebar);
            else if (ridx == 1) red_tile_w1(acc, kb, vb, lane, ebar);
            else if (ridx == 2) red_tile_w2(acc, kb, vb, lane, ebar);
            else                red_tile_w3(acc, kb, vb, lane, ebar);

            stage++; if (stage == DEPTH) { stage = 0; phase ^= 1; }
        }

        const int cnt = RW_CNT[ridx];
        for (int b = 0; b < cnt; b++) {
            const int enc = RW_TBL[ridx][b];
            const int src = (enc >> 4) & 1, ar = (enc >> 2) & 3, ac = enc & 3;
            float* gd = src ? g_G2 : g_G1;
            const int r0 = (ar * 16 + lp) * D + ac * 16;
            const int r1 = (ar * 16 + 8 + lp) * D + ac * 16;
            atomicAdd(&gd[r0 + 2 * lq],         acc[b][0]);
            atomicAdd(&gd[r0 + 2 * lq + 1],     acc[b][1]);
            atomicAdd(&gd[r1 + 2 * lq],         acc[b][2]);
            atomicAdd(&gd[r1 + 2 * lq + 1],     acc[b][3]);
            atomicAdd(&gd[r0 + 8 + 2 * lq],     acc[b][4]);
            atomicAdd(&gd[r0 + 8 + 2 * lq + 1], acc[b][5]);
            atomicAdd(&gd[r1 + 8 + 2 * lq],     acc[b][6]);
            atomicAdd(&gd[r1 + 8 + 2 * lq + 1], acc[b][7]);
        }
    }
}

// gates helper: warps 0-2 each compute one gate (identical across blocks)
__device__ __forceinline__ void compute_gates(float* gates_sh, const float* gate_w,
                                              const float* gate_b, int warp, int lane, int N) {
    if (warp < 3) {
        const float invN = 1.0f / (float)N;
        float s = gate_w[warp * D + lane]      * (g_ksum[lane]      * invN)
                + gate_w[warp * D + 32 + lane] * (g_ksum[32 + lane] * invN);
#pragma unroll
        for (int off = 16; off > 0; off >>= 1)
            s += __shfl_xor_sync(0xFFFFFFFF, s, off);
        if (lane == 0)
            gates_sh[warp] = 1.0f / (1.0f + __expf(-(s + gate_b[warp])));
    }
}

// final1: 32 blocks x 128 threads
__global__ void titans_final1(const float* __restrict__ W,
                              const float* __restrict__ gate_w,
                              const float* __restrict__ gate_b,
                              const float* __restrict__ S,
                              float* __restrict__ out,
                              int N) {
    __shared__ float G1m[D * D];
    __shared__ float W2[2 * D];
    __shared__ float gates_sh[3];
    __shared__ float red[128], red2[128];
    const int tid  = threadIdx.x;
    const int bid  = blockIdx.x;
    const int lane = tid & 31;
    const int warp = tid >> 5;
    const float numel = (float)N * (float)D;

    const size_t loss_off = (size_t)N * D;
    const size_t nw_off   = loss_off + 1;
    const size_t ns_off   = nw_off + D * D;

    compute_gates(gates_sh, gate_w, gate_b, warp, lane, N);

    for (int i = tid; i < D * D; i += 128) {
        const int j = i >> 6, d = i & 63;
        G1m[i] = ((j >> 4) <= (d >> 4)) ? g_G1[i] : g_G1[(d << 6) | j];
    }
    W2[tid] = W[bid * 128 + tid];
    __syncthreads();

    const float alpha = gates_sh[0];
    const float eta   = gates_sh[1];
    const float theta = gates_sh[2];

    const int idx = bid * 128 + tid;
    const int jr  = tid >> 6;
    const int dp  = idx & 63;

    float a = 0.0f;
#pragma unroll 8
    for (int d = 0; d < D; d++)
        a += W2[jr * D + d] * G1m[d * D + dp];

    const float w  = W2[jr * D + dp];
    const float g2 = g_G2[idx];
    float g = (a - g2) * (2.0f / numel);
    g = fminf(1.0f, fmaxf(-1.0f, g));
    const float ns = eta * S[idx] - 0.01f * theta * g;
    const float nw = (1.0f - alpha) * w + ns;
    out[ns_off + idx] = ns;
    out[nw_off + idx] = nw;

    red[tid]  = nw * nw;
    red2[tid] = (a - 2.0f * g2) * w;
    __syncthreads();
#pragma unroll
    for (int s = 64; s > 0; s >>= 1) {
        if (tid < s) { red[tid] += red[tid + s]; red2[tid] += red2[tid + s]; }
        __syncthreads();
    }
    if (tid == 0) {
        atomicAdd(&g_ss, red[0]);
        atomicAdd(&g_dl, red2[0]);
    }
}

// final2: 1 block — scale new_W, loss, gates, re-zero scratch
__global__ void titans_final2(const float* __restrict__ gate_w,
                              const float* __restrict__ gate_b,
                              float* __restrict__ out,
                              int N) {
    __shared__ float gates_sh[3];
    __shared__ float sc_sh;
    const int tid  = threadIdx.x;
    const int lane = tid & 31;
    const int warp = tid >> 5;
    const float numel = (float)N * (float)D;

    const size_t loss_off = (size_t)N * D;
    const size_t nw_off   = loss_off + 1;
    const size_t g_off    = nw_off + 2 * D * D;

    compute_gates(gates_sh, gate_w, gate_b, warp, lane, N);
    if (tid == 0) {
        float wnorm = sqrtf(g_ss);
        sc_sh = (wnorm > 10.0f) ? (10.0f / (wnorm + 1e-8f)) : 1.0f;
        out[loss_off] = (g_sv + g_dl) / numel;
    }
    __syncthreads();
    const float sc = sc_sh;
    for (int i = tid; i < D * D; i += 256)
        out[nw_off + i] *= sc;
    if (tid < 3) out[g_off + tid] = gates_sh[tid];

    __syncthreads();
    for (int i = tid; i < D * D; i += 256) { g_G1[i] = 0.0f; g_G2[i] = 0.0f; }
    if (tid < D) g_ksum[tid] = 0.0f;
    if (tid == 0) { g_sv = 0.0f; g_ss = 0.0f; g_dl = 0.0f; }
}

extern "C" void kernel_launch(void* const* d_in, const int* in_sizes, int n_in,
                              void* d_out, int out_size) {
    const float* k  = (const float*)d_in[0];
    const float* v  = (const float*)d_in[1];
    const float* W  = (const float*)d_in[2];
    const float* gw = (const float*)d_in[3];
    const float* gb = (const float*)d_in[4];
    const float* S  = (const float*)d_in[5];
    float* out = (float*)d_out;

    const int N = in_sizes[0] / D;

    cudaFuncSetAttribute(titans_main_kernel,
                         cudaFuncAttributeMaxDynamicSharedMemorySize, SMEM_BYTES);

    titans_main_kernel<<<148, 512, SMEM_BYTES>>>(k, v, W, out, N);
    titans_final1<<<32, 128>>>(W, gw, gb, S, out, N);
    titans_final2<<<1, 256>>>(gw, gb, out, N);
}